// round 7
// baseline (speedup 1.0000x reference)
#include <cuda_runtime.h>
#include <stdint.h>

#define D_    64
#define H_    32
#define W_    32
#define CIN_  128
#define COUT_ 128
#define NPIX  (D_*H_*W_)     // 65536
#define KOFF  1152
#define ROWS  4
#define PACKX_BLOCKS (NPIX/64)    // 1024 (one 32-bit word per thread)
#define PACKW_BLOCKS (D_*9)       // 576

// -------- scratch (no allocations allowed) --------
__device__ __align__(16) uint32_t g_xb[NPIX*4];   // packed x bits: 4 words / pixel
__device__ uint4 g_wb[D_*9*COUT_];                // packed w bits per (d,tap,cout)

// bytes of v are 0/1: returns b0 | b1<<1 | b2<<2 | b3<<3
__device__ __forceinline__ uint32_t nib(uint32_t v){
    return (v | (v >> 7) | (v >> 14) | (v >> 21)) & 0xFu;
}

// Fused packing kernel.
// Blocks [0,1024): pack x — one thread packs one 32-channel word.
// Blocks [1024,1600): pack w via smem transpose + ballot.
__global__ __launch_bounds__(256)
void pack_kernel(const uint8_t* __restrict__ x, const float* __restrict__ w){
    __shared__ union {
        struct { float tile[32][129]; uint32_t wword[4][128]; } pw;
        int mode;
    } sm;
    int tid = threadIdx.x;

    if (blockIdx.x < PACKX_BLOCKS){
        // dtype probe: warp 0 scans first 4KB (L2-broadcast across blocks)
        if (tid < 32){
            const uint4* p4 = reinterpret_cast<const uint4*>(x);
            int gt1 = 0, nz = 0;
            for (int i = tid; i < 256; i += 32){
                uint4 a = p4[i];
                uint32_t r[4] = {a.x, a.y, a.z, a.w};
                #pragma unroll
                for (int e = 0; e < 4; e++){
                    if (r[e] & 0xFEFEFEFEu) gt1 = 1;   // any byte >1 -> 32-bit fp/int? no: fp32/bf16
                    if (r[e] & 0xFFFFFF00u) nz  = 1;   // nonzero off word-pos
                }
            }
            gt1 = __reduce_or_sync(0xFFFFFFFFu, gt1);
            nz  = __reduce_or_sync(0xFFFFFFFFu, nz);
            // mode: 0=uint8, 1=32-bit elems (int32 OR float32: same !=0 path), 3=bf16
            if (tid == 0) sm.mode = (!gt1) ? (nz ? 0 : 1) : ((nz) ? 3 : 1);
        }
        __syncthreads();
        int mode = sm.mode;
        int gid = blockIdx.x * 256 + tid;
        int p = gid >> 2, k = gid & 3;         // pixel, word index
        uint32_t v = 0;
        if (mode == 1){                        // 32-bit 0/1 elems (int32 or float32)
            const uint4* pi = reinterpret_cast<const uint4*>(x) + (size_t)p * 32 + k * 8;
            #pragma unroll
            for (int q = 0; q < 8; q++){
                uint4 a = pi[q];
                v |= (a.x ? 1u : 0u) << (q*4 + 0);
                v |= (a.y ? 1u : 0u) << (q*4 + 1);
                v |= (a.z ? 1u : 0u) << (q*4 + 2);
                v |= (a.w ? 1u : 0u) << (q*4 + 3);
            }
        } else if (mode == 0){                 // uint8 bool
            const uint4* px = reinterpret_cast<const uint4*>(x) + (size_t)p * 8 + k * 2;
            uint4 a = px[0], b = px[1];
            v = nib(a.x)        | (nib(a.y) << 4)  | (nib(a.z) << 8)  | (nib(a.w) << 12)
              | (nib(b.x) << 16)| (nib(b.y) << 20) | (nib(b.z) << 24) | (nib(b.w) << 28);
        } else {                               // bf16 0/1 (nonzero halfword = 1)
            const uint4* pb = reinterpret_cast<const uint4*>(x) + (size_t)p * 16 + k * 4;
            #pragma unroll
            for (int q = 0; q < 4; q++){
                uint4 a = pb[q];
                uint32_t r[4] = {a.x, a.y, a.z, a.w};
                #pragma unroll
                for (int e = 0; e < 4; e++){
                    v |= ((r[e] & 0x0000FFFFu) ? 1u : 0u) << (q*8 + e*2 + 0);
                    v |= ((r[e] & 0xFFFF0000u) ? 1u : 0u) << (q*8 + e*2 + 1);
                }
            }
        }
        g_xb[gid] = v;                         // warp writes 128B line
    } else {
        // ---- pack w: one block per (d,tap); smem transpose + ballot ----
        int dt   = blockIdx.x - PACKX_BLOCKS;  // d*9 + tap
        int lane = tid & 31, warp = tid >> 5;
        const float* wp = w + (size_t)dt * (CIN_ * COUT_);
        #pragma unroll
        for (int chunk = 0; chunk < 4; chunk++){
            __syncthreads();
            #pragma unroll
            for (int e = 0; e < 16; e++){
                int idx = e * 256 + tid;       // 32 cin-rows x 128 cout
                sm.pw.tile[idx >> 7][idx & 127] = wp[chunk * 4096 + idx];
            }
            __syncthreads();
            #pragma unroll
            for (int k = 0; k < 16; k++){
                int c = warp * 16 + k;         // cout; lane = cin bit
                uint32_t b = __ballot_sync(0xFFFFFFFFu, sm.pw.tile[lane][c] != 0.0f);
                if (lane == 0) sm.pw.wword[chunk][c] = b;
            }
        }
        __syncthreads();
        if (tid < 128)
            g_wb[dt * COUT_ + tid] = make_uint4(sm.pw.wword[0][tid], sm.pw.wword[1][tid],
                                                sm.pw.wword[2][tid], sm.pw.wword[3][tid]);
    }
}

// Conv via XOR identity: out = K - 2*sum_taps popc(x ^ w).
// Thread (co,g) processes the row pair {2g, 2g+1} at each pc:
// 12 shared x loads per 2 pixels, 8 independent popc-accumulate chains.
__global__ __launch_bounds__(256)
void conv_kernel(float* __restrict__ out){
    __shared__ uint4 xs[ROWS + 2][W_ + 2];
    int tid = threadIdx.x;
    int co  = tid & 127;
    int g   = tid >> 7;            // row-pair select
    int d   = blockIdx.y;
    int r0  = blockIdx.x * ROWS;

    // x tile with zero halo
    const uint4* xb4 = reinterpret_cast<const uint4*>(g_xb);
    for (int i = tid; i < (ROWS + 2) * (W_ + 2); i += 256){
        int rr = i / (W_ + 2), cc = i % (W_ + 2);
        int hh = r0 - 1 + rr, ww = cc - 1;
        uint4 v = make_uint4(0u, 0u, 0u, 0u);
        if ((unsigned)hh < H_ && (unsigned)ww < W_)
            v = xb4[(d * H_ + hh) * W_ + ww];
        xs[rr][cc] = v;
    }

    uint4 wr[9];
    #pragma unroll
    for (int t = 0; t < 9; t++)
        wr[t] = g_wb[(d * 9 + t) * COUT_ + co];
    __syncthreads();

    int rbase = 2 * g;             // block-local pixel rows {rbase, rbase+1}
    float* rowA = out + ((size_t)(d * H_ + r0 + rbase)     * W_) * COUT_ + co;
    float* rowB = out + ((size_t)(d * H_ + r0 + rbase + 1) * W_) * COUT_ + co;

    for (int pc = 0; pc < W_; pc++){
        int a0 = 0, a1 = 0, a2 = 0, a3 = 0;   // pixel A = row rbase
        int b0 = 0, b1 = 0, b2 = 0, b3 = 0;   // pixel B = row rbase+1
        #pragma unroll
        for (int j = 0; j < 4; j++){           // xs rows rbase+j
            #pragma unroll
            for (int i = 0; i < 3; i++){
                uint4 xv = xs[rbase + j][pc + i];
                if (j < 3){                    // pixel A tap (j, i)
                    uint4 wv = wr[j * 3 + i];
                    a0 += __popc(xv.x ^ wv.x); a1 += __popc(xv.y ^ wv.y);
                    a2 += __popc(xv.z ^ wv.z); a3 += __popc(xv.w ^ wv.w);
                }
                if (j >= 1){                   // pixel B tap (j-1, i)
                    uint4 wv = wr[(j - 1) * 3 + i];
                    b0 += __popc(xv.x ^ wv.x); b1 += __popc(xv.y ^ wv.y);
                    b2 += __popc(xv.z ^ wv.z); b3 += __popc(xv.w ^ wv.w);
                }
            }
        }
        rowA[(size_t)pc * COUT_] = (float)(KOFF - 2 * ((a0 + a1) + (a2 + a3)));
        rowB[(size_t)pc * COUT_] = (float)(KOFF - 2 * ((b0 + b1) + (b2 + b3)));
    }
}

extern "C" void kernel_launch(void* const* d_in, const int* in_sizes, int n_in,
                              void* d_out, int out_size){
    const void* in0 = d_in[0];
    const void* in1 = d_in[1];
    // defensive: identify x vs w (9437184 elems) by size
    if (in_sizes[0] == D_*9*CIN_*COUT_) { const void* t = in0; in0 = in1; in1 = t; }
    const uint8_t* x = (const uint8_t*)in0;
    const float*   w = (const float*)in1;
    float* out = (float*)d_out;

    pack_kernel<<<PACKX_BLOCKS + PACKW_BLOCKS, 256>>>(x, w);
    conv_kernel<<<dim3(H_ / ROWS, D_), 256>>>(out);
}

// round 8
// speedup vs baseline: 1.2303x; 1.2303x over previous
#include <cuda_runtime.h>
#include <stdint.h>

#define D_    64
#define H_    32
#define W_    32
#define CIN_  128
#define COUT_ 128
#define NPIX  (D_*H_*W_)     // 65536
#define KOFF  1152
#define ROWS  4
#define PACKX_BLOCKS (NPIX/256)   // 256
#define PACKW_BLOCKS (D_*9)       // 576

// -------- scratch (no allocations allowed) --------
__device__ uint4 g_xb[NPIX];            // packed x bits: 128 bits / pixel
__device__ uint4 g_wb[D_*9*COUT_];      // packed w bits per (d,tap,cout)

// bytes of v are 0/1: returns b0 | b1<<1 | b2<<2 | b3<<3
__device__ __forceinline__ uint32_t nib(uint32_t v){
    return (v | (v >> 7) | (v >> 14) | (v >> 21)) & 0xFu;
}

// carry-save adder primitives: any 3-input boolean = one LOP3
__device__ __forceinline__ uint32_t xor3(uint32_t a, uint32_t b, uint32_t c){
    uint32_t r;
    asm("lop3.b32 %0, %1, %2, %3, 0x96;" : "=r"(r) : "r"(a), "r"(b), "r"(c));
    return r;
}
__device__ __forceinline__ uint32_t maj3(uint32_t a, uint32_t b, uint32_t c){
    uint32_t r;
    asm("lop3.b32 %0, %1, %2, %3, 0xE8;" : "=r"(r) : "r"(a), "r"(b), "r"(c));
    return r;
}

// Fused packing kernel. Blocks [0,256): pack x (dtype-probed).
// Blocks [256,832): pack w via smem transpose + ballot.
__global__ __launch_bounds__(256)
void pack_kernel(const uint8_t* __restrict__ x, const float* __restrict__ w){
    __shared__ union {
        struct { float tile[32][129]; uint32_t wword[4][128]; } pw;
        int mode;
    } sm;
    int tid = threadIdx.x;

    if (blockIdx.x < PACKX_BLOCKS){
        // ---- pack x: one thread per pixel, contiguous 128B per thread ----
        if (tid < 32){
            const uint4* p4 = reinterpret_cast<const uint4*>(x);
            int gt1 = 0, nz = 0, bf = 0;
            for (int i = tid; i < 256; i += 32){
                uint4 a = p4[i];
                uint32_t r[4] = {a.x, a.y, a.z, a.w};
                #pragma unroll
                for (int e = 0; e < 4; e++){
                    uint32_t v = r[e];
                    if (v & 0xFEFEFEFEu)            gt1 = 1;  // any byte >1
                    if (v & 0xFFFFFF00u)            nz  = 1;  // nonzero off word-pos
                    if (((v >> 8) & 0xFFu) == 0x3F) bf  = 1;  // bf16 signature
                }
            }
            gt1 = __reduce_or_sync(0xFFFFFFFFu, gt1);
            nz  = __reduce_or_sync(0xFFFFFFFFu, nz);
            bf  = __reduce_or_sync(0xFFFFFFFFu, bf);
            if (tid == 0) sm.mode = (!gt1) ? (nz ? 0 : 1) : (bf ? 3 : 2);
        }
        __syncthreads();
        int mode = sm.mode;            // 0=uint8, 1=int32, 2=float32, 3=bf16
        int p = blockIdx.x * 256 + tid;
        uint32_t wd[4];
        if (mode == 1){                // int32 0/1 (observed)
            const uint4* pi = reinterpret_cast<const uint4*>(x) + (size_t)p * 32;
            #pragma unroll
            for (int k = 0; k < 4; k++){
                uint32_t v = 0;
                #pragma unroll
                for (int q = 0; q < 8; q++){
                    uint4 a = pi[k*8 + q];
                    v |= (a.x ? 1u : 0u) << (q*4 + 0);
                    v |= (a.y ? 1u : 0u) << (q*4 + 1);
                    v |= (a.z ? 1u : 0u) << (q*4 + 2);
                    v |= (a.w ? 1u : 0u) << (q*4 + 3);
                }
                wd[k] = v;
            }
        } else if (mode == 0){         // uint8 bool
            const uint4* px = reinterpret_cast<const uint4*>(x) + (size_t)p * 8;
            #pragma unroll
            for (int k = 0; k < 4; k++){
                uint4 a = px[2*k], b = px[2*k+1];
                wd[k] = nib(a.x)        | (nib(a.y) << 4)  | (nib(a.z) << 8)  | (nib(a.w) << 12)
                      | (nib(b.x) << 16)| (nib(b.y) << 20) | (nib(b.z) << 24) | (nib(b.w) << 28);
            }
        } else if (mode == 2){         // float32 0/1
            const float4* pf = reinterpret_cast<const float4*>(x) + (size_t)p * 32;
            #pragma unroll
            for (int k = 0; k < 4; k++){
                uint32_t v = 0;
                #pragma unroll
                for (int q = 0; q < 8; q++){
                    float4 f = pf[k*8 + q];
                    v |= (f.x != 0.0f ? 1u : 0u) << (q*4 + 0);
                    v |= (f.y != 0.0f ? 1u : 0u) << (q*4 + 1);
                    v |= (f.z != 0.0f ? 1u : 0u) << (q*4 + 2);
                    v |= (f.w != 0.0f ? 1u : 0u) << (q*4 + 3);
                }
                wd[k] = v;
            }
        } else {                       // bf16 0/1
            const uint4* pb = reinterpret_cast<const uint4*>(x) + (size_t)p * 16;
            #pragma unroll
            for (int k = 0; k < 4; k++){
                uint32_t v = 0;
                #pragma unroll
                for (int q = 0; q < 4; q++){
                    uint4 a = pb[k*4 + q];
                    uint32_t r[4] = {a.x, a.y, a.z, a.w};
                    #pragma unroll
                    for (int e = 0; e < 4; e++){
                        v |= ((r[e] & 0x7FFFu)     ? 1u : 0u) << (q*8 + e*2 + 0);
                        v |= ((r[e] & 0x7FFF0000u) ? 1u : 0u) << (q*8 + e*2 + 1);
                    }
                }
                wd[k] = v;
            }
        }
        g_xb[p] = make_uint4(wd[0], wd[1], wd[2], wd[3]);
    } else {
        // ---- pack w: one block per (d,tap); smem transpose + ballot ----
        int dt   = blockIdx.x - PACKX_BLOCKS;   // d*9 + tap
        int lane = tid & 31, warp = tid >> 5;
        const float* wp = w + (size_t)dt * (CIN_ * COUT_);
        #pragma unroll
        for (int chunk = 0; chunk < 4; chunk++){
            __syncthreads();
            #pragma unroll
            for (int e = 0; e < 16; e++){
                int idx = e * 256 + tid;            // 32 cin-rows x 128 cout
                sm.pw.tile[idx >> 7][idx & 127] = wp[chunk * 4096 + idx];
            }
            __syncthreads();
            #pragma unroll
            for (int k = 0; k < 16; k++){
                int c = warp * 16 + k;              // cout; lane = cin bit
                uint32_t b = __ballot_sync(0xFFFFFFFFu, sm.pw.tile[lane][c] != 0.0f);
                if (lane == 0) sm.pw.wword[chunk][c] = b;
            }
        }
        __syncthreads();
        if (tid < 128)
            g_wb[dt * COUT_ + tid] = make_uint4(sm.pw.wword[0][tid], sm.pw.wword[1][tid],
                                                sm.pw.wword[2][tid], sm.pw.wword[3][tid]);
    }
}

// Conv via XOR identity + carry-save adder tree:
// out = K - 2 * sum_{36 words} popc(x ^ w); the 36 popcounts are compressed
// through CSA layers (full-rate LOP3) down to 7 POPCs.
__global__ __launch_bounds__(256)
void conv_kernel(float* __restrict__ out){
    __shared__ uint4 xs[ROWS + 2][W_ + 2];
    int tid = threadIdx.x;
    int co  = tid & 127;
    int g   = tid >> 7;            // 2 pixel groups
    int d   = blockIdx.y;
    int r0  = blockIdx.x * ROWS;

    // x tile with zero halo
    for (int i = tid; i < (ROWS + 2) * (W_ + 2); i += 256){
        int rr = i / (W_ + 2), cc = i % (W_ + 2);
        int hh = r0 - 1 + rr, ww = cc - 1;
        uint4 v = make_uint4(0u, 0u, 0u, 0u);
        if ((unsigned)hh < H_ && (unsigned)ww < W_)
            v = g_xb[(d * H_ + hh) * W_ + ww];
        xs[rr][cc] = v;
    }

    uint32_t wr[9][4];
    #pragma unroll
    for (int t = 0; t < 9; t++){
        uint4 v = g_wb[(d * 9 + t) * COUT_ + co];
        wr[t][0] = v.x; wr[t][1] = v.y; wr[t][2] = v.z; wr[t][3] = v.w;
    }
    __syncthreads();

    float* outp = out + ((size_t)(d * H_ + r0) * W_) * COUT_ + co;
    #pragma unroll 2
    for (int p = g; p < ROWS * W_; p += 2){
        int pr = p >> 5, pc = p & 31;

        uint32_t S[4], C1[4], S2[4], C2[4];
        #pragma unroll
        for (int k = 0; k < 4; k++){
            uint32_t v[9];
            #pragma unroll
            for (int t = 0; t < 9; t++){
                const uint32_t* xw = reinterpret_cast<const uint32_t*>(&xs[pr + t / 3][pc + t % 3]);
                v[t] = xw[k] ^ wr[t][k];
            }
            uint32_t sa = xor3(v[0], v[1], v[2]), ca = maj3(v[0], v[1], v[2]);
            uint32_t sb = xor3(v[3], v[4], v[5]), cb = maj3(v[3], v[4], v[5]);
            uint32_t sc = xor3(v[6], v[7], v[8]), cc = maj3(v[6], v[7], v[8]);
            S [k] = xor3(sa, sb, sc);  C1[k] = maj3(sa, sb, sc);   // w1, w2
            S2[k] = xor3(ca, cb, cc);  C2[k] = maj3(ca, cb, cc);   // w2, w4
        }
        // w1 pool: S[0..3]
        uint32_t sA = xor3(S[0], S[1], S[2]), cA = maj3(S[0], S[1], S[2]);
        int P1 = __popc(sA) + __popc(S[3]);
        // w2 pool: C1[0..3], S2[0..3], cA  (9 words)
        uint32_t t0 = xor3(C1[0], C1[1], C1[2]), u0 = maj3(C1[0], C1[1], C1[2]);
        uint32_t t1 = xor3(C1[3], S2[0], S2[1]), u1 = maj3(C1[3], S2[0], S2[1]);
        uint32_t t2 = xor3(S2[2], S2[3], cA),    u2 = maj3(S2[2], S2[3], cA);
        uint32_t t3 = xor3(t0, t1, t2),          u3 = maj3(t0, t1, t2);
        int P2 = __popc(t3);
        // w4 pool: C2[0..3], u0..u3  (8 words)
        uint32_t q0 = xor3(C2[0], C2[1], C2[2]), r0w = maj3(C2[0], C2[1], C2[2]);
        uint32_t q1 = xor3(C2[3], u0, u1),       r1w = maj3(C2[3], u0, u1);
        uint32_t q2 = xor3(u2, u3, q0),          r2w = maj3(u2, u3, q0);
        int P4 = __popc(q1) + __popc(q2);
        // w8 pool: r0w, r1w, r2w
        uint32_t s8 = xor3(r0w, r1w, r2w), c16 = maj3(r0w, r1w, r2w);
        int P8  = __popc(s8);
        int P16 = __popc(c16);

        int acc = P1 + 2*P2 + 4*P4 + 8*P8 + 16*P16;
        outp[(size_t)p * COUT_] = (float)(KOFF - 2 * acc);
    }
}

extern "C" void kernel_launch(void* const* d_in, const int* in_sizes, int n_in,
                              void* d_out, int out_size){
    const void* in0 = d_in[0];
    const void* in1 = d_in[1];
    // defensive: identify x vs w (9437184 elems) by size
    if (in_sizes[0] == D_*9*CIN_*COUT_) { const void* t = in0; in0 = in1; in1 = t; }
    const uint8_t* x = (const uint8_t*)in0;
    const float*   w = (const float*)in1;
    float* out = (float*)d_out;

    pack_kernel<<<PACKX_BLOCKS + PACKW_BLOCKS, 256>>>(x, w);
    conv_kernel<<<dim3(H_ / ROWS, D_), 256>>>(out);
}

// round 9
// speedup vs baseline: 1.2623x; 1.0260x over previous
#include <cuda_runtime.h>
#include <stdint.h>

#define D_    64
#define H_    32
#define W_    32
#define CIN_  128
#define COUT_ 128
#define NPIX  (D_*H_*W_)     // 65536
#define KOFF  1152
#define ROWS  4
#define PACKX_BLOCKS (NPIX/256)   // 256
#define PACKW_BLOCKS (D_*9*2)     // 1152 (one block per (d,tap,chunk-half))

// -------- scratch (no allocations allowed) --------
__device__ uint4 g_xb[NPIX];            // packed x bits: 128 bits / pixel
__device__ uint4 g_wb[D_*9*COUT_];      // packed w bits per (d,tap,cout)

// bytes of v are 0/1: returns b0 | b1<<1 | b2<<2 | b3<<3
__device__ __forceinline__ uint32_t nib(uint32_t v){
    return (v | (v >> 7) | (v >> 14) | (v >> 21)) & 0xFu;
}

// carry-save adder primitives: any 3-input boolean = one LOP3
__device__ __forceinline__ uint32_t xor3(uint32_t a, uint32_t b, uint32_t c){
    uint32_t r;
    asm("lop3.b32 %0, %1, %2, %3, 0x96;" : "=r"(r) : "r"(a), "r"(b), "r"(c));
    return r;
}
__device__ __forceinline__ uint32_t maj3(uint32_t a, uint32_t b, uint32_t c){
    uint32_t r;
    asm("lop3.b32 %0, %1, %2, %3, 0xE8;" : "=r"(r) : "r"(a), "r"(b), "r"(c));
    return r;
}

// Fused packing kernel.
// Blocks [0,256): pack x (dtype-probed), one thread per pixel.
// Blocks [256,1408): pack w, one thread per (cout,chunk) 32-bit word,
//                    32 coalesced LDG.32 + shift-or, no smem/sync.
__global__ __launch_bounds__(256)
void pack_kernel(const uint8_t* __restrict__ x, const float* __restrict__ w){
    __shared__ int mode_s;
    int tid = threadIdx.x;

    if (blockIdx.x < PACKX_BLOCKS){
        // ---- pack x ----
        if (tid < 32){
            const uint4* p4 = reinterpret_cast<const uint4*>(x);
            int gt1 = 0, nz = 0, bf = 0;
            for (int i = tid; i < 256; i += 32){
                uint4 a = p4[i];
                uint32_t r[4] = {a.x, a.y, a.z, a.w};
                #pragma unroll
                for (int e = 0; e < 4; e++){
                    uint32_t v = r[e];
                    if (v & 0xFEFEFEFEu)            gt1 = 1;  // any byte >1
                    if (v & 0xFFFFFF00u)            nz  = 1;  // nonzero off word-pos
                    if (((v >> 8) & 0xFFu) == 0x3F) bf  = 1;  // bf16 signature
                }
            }
            gt1 = __reduce_or_sync(0xFFFFFFFFu, gt1);
            nz  = __reduce_or_sync(0xFFFFFFFFu, nz);
            bf  = __reduce_or_sync(0xFFFFFFFFu, bf);
            if (tid == 0) mode_s = (!gt1) ? (nz ? 0 : 1) : (bf ? 3 : 2);
        }
        __syncthreads();
        int mode = mode_s;             // 0=uint8, 1=int32, 2=float32, 3=bf16
        int p = blockIdx.x * 256 + tid;
        uint32_t wd[4];
        if (mode == 1){                // int32 0/1 (observed)
            const uint4* pi = reinterpret_cast<const uint4*>(x) + (size_t)p * 32;
            #pragma unroll
            for (int k = 0; k < 4; k++){
                uint32_t v = 0;
                #pragma unroll
                for (int q = 0; q < 8; q++){
                    uint4 a = pi[k*8 + q];
                    v |= (a.x ? 1u : 0u) << (q*4 + 0);
                    v |= (a.y ? 1u : 0u) << (q*4 + 1);
                    v |= (a.z ? 1u : 0u) << (q*4 + 2);
                    v |= (a.w ? 1u : 0u) << (q*4 + 3);
                }
                wd[k] = v;
            }
        } else if (mode == 0){         // uint8 bool
            const uint4* px = reinterpret_cast<const uint4*>(x) + (size_t)p * 8;
            #pragma unroll
            for (int k = 0; k < 4; k++){
                uint4 a = px[2*k], b = px[2*k+1];
                wd[k] = nib(a.x)        | (nib(a.y) << 4)  | (nib(a.z) << 8)  | (nib(a.w) << 12)
                      | (nib(b.x) << 16)| (nib(b.y) << 20) | (nib(b.z) << 24) | (nib(b.w) << 28);
            }
        } else if (mode == 2){         // float32 0/1
            const float4* pf = reinterpret_cast<const float4*>(x) + (size_t)p * 32;
            #pragma unroll
            for (int k = 0; k < 4; k++){
                uint32_t v = 0;
                #pragma unroll
                for (int q = 0; q < 8; q++){
                    float4 f = pf[k*8 + q];
                    v |= (f.x != 0.0f ? 1u : 0u) << (q*4 + 0);
                    v |= (f.y != 0.0f ? 1u : 0u) << (q*4 + 1);
                    v |= (f.z != 0.0f ? 1u : 0u) << (q*4 + 2);
                    v |= (f.w != 0.0f ? 1u : 0u) << (q*4 + 3);
                }
                wd[k] = v;
            }
        } else {                       // bf16 0/1
            const uint4* pb = reinterpret_cast<const uint4*>(x) + (size_t)p * 16;
            #pragma unroll
            for (int k = 0; k < 4; k++){
                uint32_t v = 0;
                #pragma unroll
                for (int q = 0; q < 4; q++){
                    uint4 a = pb[k*4 + q];
                    uint32_t r[4] = {a.x, a.y, a.z, a.w};
                    #pragma unroll
                    for (int e = 0; e < 4; e++){
                        v |= ((r[e] & 0x7FFFu)     ? 1u : 0u) << (q*8 + e*2 + 0);
                        v |= ((r[e] & 0x7FFF0000u) ? 1u : 0u) << (q*8 + e*2 + 1);
                    }
                }
                wd[k] = v;
            }
        }
        g_xb[p] = make_uint4(wd[0], wd[1], wd[2], wd[3]);
    } else {
        // ---- pack w: transpose-free ----
        int b     = blockIdx.x - PACKX_BLOCKS;      // (dt, chunk-half)
        int dt    = b >> 1;                          // d*9 + tap
        int co    = tid & 127;                       // lane-consecutive couts
        int chunk = ((b & 1) << 1) + (tid >> 7);     // 0..3
        const float* wp = w + (size_t)dt * (CIN_ * COUT_) + (size_t)chunk * 32 * COUT_;
        uint32_t v = 0;
        #pragma unroll
        for (int ci = 0; ci < 32; ci++)
            v |= (wp[ci * COUT_ + co] != 0.0f ? 1u : 0u) << ci;
        reinterpret_cast<uint32_t*>(g_wb)[(dt * COUT_ + co) * 4 + chunk] = v;
    }
}

// Conv via XOR identity + CSA tree: out = K - 2 * sum_{36} popc(x ^ w),
// 36 popcounts compressed to 7 POPC via full-rate LOP3 full-adders.
// Block = 128 threads (1/cout); all 512 CTAs resident in one wave.
__global__ __launch_bounds__(128)
void conv_kernel(float* __restrict__ out){
    __shared__ uint4 xs[ROWS + 2][W_ + 2];
    int co = threadIdx.x;          // 0..127
    int d  = blockIdx.y;
    int r0 = blockIdx.x * ROWS;

    // x tile with zero halo
    for (int i = co; i < (ROWS + 2) * (W_ + 2); i += 128){
        int rr = i / (W_ + 2), cc = i % (W_ + 2);
        int hh = r0 - 1 + rr, ww = cc - 1;
        uint4 v = make_uint4(0u, 0u, 0u, 0u);
        if ((unsigned)hh < H_ && (unsigned)ww < W_)
            v = g_xb[(d * H_ + hh) * W_ + ww];
        xs[rr][cc] = v;
    }

    uint32_t wr[9][4];
    #pragma unroll
    for (int t = 0; t < 9; t++){
        uint4 v = g_wb[(d * 9 + t) * COUT_ + co];
        wr[t][0] = v.x; wr[t][1] = v.y; wr[t][2] = v.z; wr[t][3] = v.w;
    }
    __syncthreads();

    float* outp = out + ((size_t)(d * H_ + r0) * W_) * COUT_ + co;
    #pragma unroll 2
    for (int p = 0; p < ROWS * W_; p++){
        int pr = p >> 5, pc = p & 31;

        uint32_t S[4], C1[4], S2[4], C2[4];
        #pragma unroll
        for (int k = 0; k < 4; k++){
            uint32_t v[9];
            #pragma unroll
            for (int t = 0; t < 9; t++){
                const uint32_t* xw = reinterpret_cast<const uint32_t*>(&xs[pr + t / 3][pc + t % 3]);
                v[t] = xw[k] ^ wr[t][k];
            }
            uint32_t sa = xor3(v[0], v[1], v[2]), ca = maj3(v[0], v[1], v[2]);
            uint32_t sb = xor3(v[3], v[4], v[5]), cb = maj3(v[3], v[4], v[5]);
            uint32_t sc = xor3(v[6], v[7], v[8]), cc = maj3(v[6], v[7], v[8]);
            S [k] = xor3(sa, sb, sc);  C1[k] = maj3(sa, sb, sc);   // w1, w2
            S2[k] = xor3(ca, cb, cc);  C2[k] = maj3(ca, cb, cc);   // w2, w4
        }
        // w1 pool: S[0..3]
        uint32_t sA = xor3(S[0], S[1], S[2]), cA = maj3(S[0], S[1], S[2]);
        int P1 = __popc(sA) + __popc(S[3]);
        // w2 pool: C1[0..3], S2[0..3], cA  (9 words)
        uint32_t t0 = xor3(C1[0], C1[1], C1[2]), u0 = maj3(C1[0], C1[1], C1[2]);
        uint32_t t1 = xor3(C1[3], S2[0], S2[1]), u1 = maj3(C1[3], S2[0], S2[1]);
        uint32_t t2 = xor3(S2[2], S2[3], cA),    u2 = maj3(S2[2], S2[3], cA);
        uint32_t t3 = xor3(t0, t1, t2),          u3 = maj3(t0, t1, t2);
        int P2 = __popc(t3);
        // w4 pool: C2[0..3], u0..u3  (8 words)
        uint32_t q0 = xor3(C2[0], C2[1], C2[2]), r0w = maj3(C2[0], C2[1], C2[2]);
        uint32_t q1 = xor3(C2[3], u0, u1),       r1w = maj3(C2[3], u0, u1);
        uint32_t q2 = xor3(u2, u3, q0),          r2w = maj3(u2, u3, q0);
        int P4 = __popc(q1) + __popc(q2);
        // w8 pool: r0w, r1w, r2w
        uint32_t s8 = xor3(r0w, r1w, r2w), c16 = maj3(r0w, r1w, r2w);
        int P8  = __popc(s8);
        int P16 = __popc(c16);

        int acc = P1 + 2*P2 + 4*P4 + 8*P8 + 16*P16;
        outp[(size_t)p * COUT_] = (float)(KOFF - 2 * acc);
    }
}

extern "C" void kernel_launch(void* const* d_in, const int* in_sizes, int n_in,
                              void* d_out, int out_size){
    const void* in0 = d_in[0];
    const void* in1 = d_in[1];
    // defensive: identify x vs w (9437184 elems) by size
    if (in_sizes[0] == D_*9*CIN_*COUT_) { const void* t = in0; in0 = in1; in1 = t; }
    const uint8_t* x = (const uint8_t*)in0;
    const float*   w = (const float*)in1;
    float* out = (float*)d_out;

    pack_kernel<<<PACKX_BLOCKS + PACKW_BLOCKS, 256>>>(x, w);
    conv_kernel<<<dim3(H_ / ROWS, D_), 128>>>(out);
}

// round 10
// speedup vs baseline: 1.3922x; 1.1029x over previous
#include <cuda_runtime.h>
#include <stdint.h>

#define D_    64
#define H_    32
#define W_    32
#define CIN_  128
#define COUT_ 128
#define NPIX  (D_*H_*W_)     // 65536
#define KOFF  1152
#define ROWS  2
#define PACKW_BLOCKS (D_*9*2)     // 1152

// -------- scratch (no allocations allowed) --------
__device__ uint4 g_wb[D_*9*COUT_];      // packed w bits per (d,tap,cout)
__device__ int   g_mode;                // 0=uint8, 1=32-bit(int32/f32), 3=bf16

// bytes of v are 0/1: returns b0 | b1<<1 | b2<<2 | b3<<3
__device__ __forceinline__ uint32_t nib(uint32_t v){
    return (v | (v >> 7) | (v >> 14) | (v >> 21)) & 0xFu;
}

// carry-save adder primitives: any 3-input boolean = one LOP3
__device__ __forceinline__ uint32_t xor3(uint32_t a, uint32_t b, uint32_t c){
    uint32_t r;
    asm("lop3.b32 %0, %1, %2, %3, 0x96;" : "=r"(r) : "r"(a), "r"(b), "r"(c));
    return r;
}
__device__ __forceinline__ uint32_t maj3(uint32_t a, uint32_t b, uint32_t c){
    uint32_t r;
    asm("lop3.b32 %0, %1, %2, %3, 0xE8;" : "=r"(r) : "r"(a), "r"(b), "r"(c));
    return r;
}

// Pack a pixel's 128 channels into 4 words, by dtype mode.
__device__ __forceinline__ void pack_pixel(const uint8_t* __restrict__ x,
                                           size_t pix, int mode, uint32_t wd[4]){
    if (mode == 1){                        // 32-bit elems (int32 or float32 0/1)
        const uint4* pi = reinterpret_cast<const uint4*>(x) + pix * 32;
        #pragma unroll
        for (int k = 0; k < 4; k++){
            uint32_t v = 0;
            #pragma unroll
            for (int q = 0; q < 8; q++){
                uint4 a = pi[k*8 + q];
                v |= (a.x ? 1u : 0u) << (q*4 + 0);
                v |= (a.y ? 1u : 0u) << (q*4 + 1);
                v |= (a.z ? 1u : 0u) << (q*4 + 2);
                v |= (a.w ? 1u : 0u) << (q*4 + 3);
            }
            wd[k] = v;
        }
    } else if (mode == 0){                 // uint8 bool
        const uint4* px = reinterpret_cast<const uint4*>(x) + pix * 8;
        #pragma unroll
        for (int k = 0; k < 4; k++){
            uint4 a = px[2*k], b = px[2*k+1];
            wd[k] = nib(a.x)        | (nib(a.y) << 4)  | (nib(a.z) << 8)  | (nib(a.w) << 12)
                  | (nib(b.x) << 16)| (nib(b.y) << 20) | (nib(b.z) << 24) | (nib(b.w) << 28);
        }
    } else {                               // bf16 0/1 (nonzero halfword = 1)
        const uint4* pb = reinterpret_cast<const uint4*>(x) + pix * 16;
        #pragma unroll
        for (int k = 0; k < 4; k++){
            uint32_t v = 0;
            #pragma unroll
            for (int q = 0; q < 4; q++){
                uint4 a = pb[k*4 + q];
                uint32_t r[4] = {a.x, a.y, a.z, a.w};
                #pragma unroll
                for (int e = 0; e < 4; e++){
                    v |= ((r[e] & 0x0000FFFFu) ? 1u : 0u) << (q*8 + e*2 + 0);
                    v |= ((r[e] & 0xFFFF0000u) ? 1u : 0u) << (q*8 + e*2 + 1);
                }
            }
            wd[k] = v;
        }
    }
}

// Kernel 1: pack w (transpose-free; one thread per (cout,chunk) word) and
// dtype-probe x (block 0, warp 0 -> g_mode).
__global__ __launch_bounds__(256)
void pack_kernel(const uint8_t* __restrict__ x, const float* __restrict__ w){
    int tid = threadIdx.x;
    if (blockIdx.x == 0 && tid < 32){
        const uint4* p4 = reinterpret_cast<const uint4*>(x);
        int gt1 = 0, nz = 0, bf = 0;
        for (int i = tid; i < 256; i += 32){
            uint4 a = p4[i];
            uint32_t r[4] = {a.x, a.y, a.z, a.w};
            #pragma unroll
            for (int e = 0; e < 4; e++){
                uint32_t v = r[e];
                if (v & 0xFEFEFEFEu)            gt1 = 1;  // any byte >1
                if (v & 0xFFFFFF00u)            nz  = 1;  // nonzero off word-pos
                if (((v >> 8) & 0xFFu) == 0x3F) bf  = 1;  // bf16 signature
            }
        }
        gt1 = __reduce_or_sync(0xFFFFFFFFu, gt1);
        nz  = __reduce_or_sync(0xFFFFFFFFu, nz);
        bf  = __reduce_or_sync(0xFFFFFFFFu, bf);
        if (tid == 0) g_mode = (!gt1) ? (nz ? 0 : 1) : (bf ? 3 : 1);
    }
    // ---- pack w ----
    int b     = blockIdx.x;                      // (dt, chunk-half)
    int dt    = b >> 1;                          // d*9 + tap
    int co    = tid & 127;                       // lane-consecutive couts
    int chunk = ((b & 1) << 1) + (tid >> 7);     // 0..3
    const float* wp = w + (size_t)dt * (CIN_ * COUT_) + (size_t)chunk * 32 * COUT_;
    uint32_t v = 0;
    #pragma unroll
    for (int ci = 0; ci < 32; ci++)
        v |= (wp[ci * COUT_ + co] != 0.0f ? 1u : 0u) << ci;
    reinterpret_cast<uint32_t*>(g_wb)[(dt * COUT_ + co) * 4 + chunk] = v;
}

// Conv: XOR identity + CSA tree, out = K - 2*sum_{36} popc(x ^ w).
// Each block packs its own x tile from raw input (memory is idle anyway).
// 1024 CTAs for near-perfect SM balance.
__global__ __launch_bounds__(128)
void conv_kernel(const uint8_t* __restrict__ x, float* __restrict__ out){
    __shared__ uint4 xs[ROWS + 2][W_ + 2];
    int co = threadIdx.x;          // 0..127
    int d  = blockIdx.y;
    int r0 = blockIdx.x * ROWS;
    int mode = g_mode;

    // pack x tile with zero halo directly from raw input
    for (int i = co; i < (ROWS + 2) * (W_ + 2); i += 128){
        int rr = i / (W_ + 2), cc = i % (W_ + 2);
        int hh = r0 - 1 + rr, ww = cc - 1;
        uint32_t wd[4] = {0u, 0u, 0u, 0u};
        if ((unsigned)hh < H_ && (unsigned)ww < W_)
            pack_pixel(x, (size_t)(d * H_ + hh) * W_ + ww, mode, wd);
        xs[rr][cc] = make_uint4(wd[0], wd[1], wd[2], wd[3]);
    }

    uint32_t wr[9][4];
    #pragma unroll
    for (int t = 0; t < 9; t++){
        uint4 v = g_wb[(d * 9 + t) * COUT_ + co];
        wr[t][0] = v.x; wr[t][1] = v.y; wr[t][2] = v.z; wr[t][3] = v.w;
    }
    __syncthreads();

    float* outp = out + ((size_t)(d * H_ + r0) * W_) * COUT_ + co;
    #pragma unroll 2
    for (int p = 0; p < ROWS * W_; p++){
        int pr = p >> 5, pc = p & 31;

        uint32_t S[4], C1[4], S2[4], C2[4];
        #pragma unroll
        for (int k = 0; k < 4; k++){
            uint32_t v[9];
            #pragma unroll
            for (int t = 0; t < 9; t++){
                const uint32_t* xw = reinterpret_cast<const uint32_t*>(&xs[pr + t / 3][pc + t % 3]);
                v[t] = xw[k] ^ wr[t][k];
            }
            uint32_t sa = xor3(v[0], v[1], v[2]), ca = maj3(v[0], v[1], v[2]);
            uint32_t sb = xor3(v[3], v[4], v[5]), cb = maj3(v[3], v[4], v[5]);
            uint32_t sc = xor3(v[6], v[7], v[8]), cc = maj3(v[6], v[7], v[8]);
            S [k] = xor3(sa, sb, sc);  C1[k] = maj3(sa, sb, sc);   // w1, w2
            S2[k] = xor3(ca, cb, cc);  C2[k] = maj3(ca, cb, cc);   // w2, w4
        }
        // w1 pool: S[0..3]
        uint32_t sA = xor3(S[0], S[1], S[2]), cA = maj3(S[0], S[1], S[2]);
        int P1 = __popc(sA) + __popc(S[3]);
        // w2 pool: C1[0..3], S2[0..3], cA  (9 words)
        uint32_t t0 = xor3(C1[0], C1[1], C1[2]), u0 = maj3(C1[0], C1[1], C1[2]);
        uint32_t t1 = xor3(C1[3], S2[0], S2[1]), u1 = maj3(C1[3], S2[0], S2[1]);
        uint32_t t2 = xor3(S2[2], S2[3], cA),    u2 = maj3(S2[2], S2[3], cA);
        uint32_t t3 = xor3(t0, t1, t2),          u3 = maj3(t0, t1, t2);
        int P2 = __popc(t3);
        // w4 pool: C2[0..3], u0..u3  (8 words)
        uint32_t q0 = xor3(C2[0], C2[1], C2[2]), r0w = maj3(C2[0], C2[1], C2[2]);
        uint32_t q1 = xor3(C2[3], u0, u1),       r1w = maj3(C2[3], u0, u1);
        uint32_t q2 = xor3(u2, u3, q0),          r2w = maj3(u2, u3, q0);
        int P4 = __popc(q1) + __popc(q2);
        // w8 pool: r0w, r1w, r2w
        uint32_t s8 = xor3(r0w, r1w, r2w), c16 = maj3(r0w, r1w, r2w);
        int P8  = __popc(s8);
        int P16 = __popc(c16);

        int acc = P1 + 2*P2 + 4*P4 + 8*P8 + 16*P16;
        outp[(size_t)p * COUT_] = (float)(KOFF - 2 * acc);
    }
}

extern "C" void kernel_launch(void* const* d_in, const int* in_sizes, int n_in,
                              void* d_out, int out_size){
    const void* in0 = d_in[0];
    const void* in1 = d_in[1];
    // defensive: identify x vs w (9437184 elems) by size
    if (in_sizes[0] == D_*9*CIN_*COUT_) { const void* t = in0; in0 = in1; in1 = t; }
    const uint8_t* x = (const uint8_t*)in0;
    const float*   w = (const float*)in1;
    float* out = (float*)d_out;

    pack_kernel<<<PACKW_BLOCKS, 256>>>(x, w);
    conv_kernel<<<dim3(H_ / ROWS, D_), 128>>>(x, out);
}